// round 3
// baseline (speedup 1.0000x reference)
#include <cuda_runtime.h>
#include <cuda_bf16.h>
#include <cstdint>

#define NTOK 65536   // B*H*W
#define DDIM 256
#define KCB  1024
#define DECAYF 0.99f
#define ONE_M_DECAY 0.01f
#define EPSF 1e-5f
#define MARGIN 8.0f

// -------- output layout (floats) --------
// out:        16,777,216   @ 0
// loss:       1            @ 16777216
// entropy:    1            @ 16777217
// encodings:  67,108,864   @ 16777218   (byte align 8)
// cluster:    1024         @ 83886082
// new_ema_w:  262,144      @ 83887106
// new_emb:    262,144      @ 84149250
#define OFF_LOSS    16777216
#define OFF_ENT     16777217
#define OFF_ENC     16777218
#define OFF_CLUSTER 83886082
#define OFF_EMAW    83887106
#define OFF_EMB     84149250

// -------- static scratch --------
__device__ float          g_flat[NTOK * DDIM];
__device__ __nv_bfloat16  g_flat_bf[NTOK * DDIM];
__device__ __nv_bfloat16  g_emb_bf[KCB * DDIM];
__device__ float          g_e2[KCB];
__device__ int            g_idx[NTOK];
__device__ int            g_counts[KCB];
__device__ int            g_start[KCB];
__device__ int            g_pos[KCB];
__device__ int            g_bucket[NTOK];
__device__ float          g_cluster[KCB];
__device__ double         g_loss;

// ================= K0: per-replay init =================
__global__ void k_init() {
    int t = threadIdx.x;
    if (t < KCB) { g_counts[t] = 0; g_pos[t] = 0; }
    if (t == 0) g_loss = 0.0;
}

// ================= K1: NCHW -> NHWC transpose + bf16 convert =================
__global__ void k_transpose(const float* __restrict__ in) {
    __shared__ float tile[32][33];
    int b = blockIdx.z;
    int hw0 = blockIdx.x * 32;
    int c0  = blockIdx.y * 32;
    int tx = threadIdx.x, ty = threadIdx.y;
#pragma unroll
    for (int j = 0; j < 4; j++) {
        int c = c0 + ty + j * 8;
        tile[ty + j * 8][tx] = in[((size_t)(b * 256 + c) << 10) + hw0 + tx];
    }
    __syncthreads();
#pragma unroll
    for (int j = 0; j < 4; j++) {
        int hw = hw0 + ty + j * 8;
        int c  = c0 + tx;
        float v = tile[tx][ty + j * 8];
        size_t o = ((size_t)(b * 1024 + hw) << 8) + c;
        g_flat[o] = v;
        g_flat_bf[o] = __float2bfloat16(v);
    }
}

// ================= K1b: embedding bf16 + ||e||^2 =================
__global__ void k_embprep(const float* __restrict__ emb) {
    int k = blockIdx.x, t = threadIdx.x;
    float v = emb[(size_t)k * DDIM + t];
    g_emb_bf[(size_t)k * DDIM + t] = __float2bfloat16(v);
    float s = v * v;
#pragma unroll
    for (int off = 16; off > 0; off >>= 1) s += __shfl_xor_sync(0xffffffffu, s, off);
    __shared__ float ws[8];
    if ((t & 31) == 0) ws[t >> 5] = s;
    __syncthreads();
    if (t == 0) {
        float tot = 0.f;
#pragma unroll
        for (int i = 0; i < 8; i++) tot += ws[i];
        g_e2[k] = tot;
    }
}

// ================= K2: bf16 tensor-core GEMM, write s = e2 - 2*dot =================
#define BM 128
#define BN 128
#define BK 32
#define PST 40

__global__ __launch_bounds__(256, 2) void k_gemm(float* __restrict__ S) {
    __shared__ __align__(16) __nv_bfloat16 As[BM * PST];
    __shared__ __align__(16) __nv_bfloat16 Bs[BN * PST];
    int tid = threadIdx.x;
    int warp = tid >> 5, lane = tid & 31;
    int m0 = blockIdx.x * BM;
    int n0 = blockIdx.y * BN;
    int wm = warp & 3, wn = warp >> 2;
    int g = lane >> 2, c = lane & 3;

    float acc[2][8][4];
#pragma unroll
    for (int a = 0; a < 2; a++)
#pragma unroll
        for (int b = 0; b < 8; b++)
#pragma unroll
            for (int d = 0; d < 4; d++) acc[a][b][d] = 0.f;

    int lrow = tid >> 2, lseg = tid & 3;

    for (int kt = 0; kt < DDIM; kt += BK) {
        __syncthreads();
#pragma unroll
        for (int p = 0; p < 2; p++) {
            int row = lrow + p * 64;
            *(uint4*)&As[row * PST + lseg * 8] =
                *(const uint4*)&g_flat_bf[(size_t)(m0 + row) * DDIM + kt + lseg * 8];
            *(uint4*)&Bs[row * PST + lseg * 8] =
                *(const uint4*)&g_emb_bf[(size_t)(n0 + row) * DDIM + kt + lseg * 8];
        }
        __syncthreads();
#pragma unroll
        for (int ks = 0; ks < 2; ks++) {
            unsigned afr[2][4], bfr[8][2];
            int kb = ks * 16;
#pragma unroll
            for (int mi = 0; mi < 2; mi++) {
                int r = wm * 32 + mi * 16;
                afr[mi][0] = *(const unsigned*)&As[(r + g)     * PST + kb + 2 * c];
                afr[mi][1] = *(const unsigned*)&As[(r + g + 8) * PST + kb + 2 * c];
                afr[mi][2] = *(const unsigned*)&As[(r + g)     * PST + kb + 2 * c + 8];
                afr[mi][3] = *(const unsigned*)&As[(r + g + 8) * PST + kb + 2 * c + 8];
            }
#pragma unroll
            for (int ni = 0; ni < 8; ni++) {
                int cc = wn * 64 + ni * 8;
                bfr[ni][0] = *(const unsigned*)&Bs[(cc + g) * PST + kb + 2 * c];
                bfr[ni][1] = *(const unsigned*)&Bs[(cc + g) * PST + kb + 2 * c + 8];
            }
#pragma unroll
            for (int mi = 0; mi < 2; mi++)
#pragma unroll
                for (int ni = 0; ni < 8; ni++) {
                    asm volatile(
                        "mma.sync.aligned.m16n8k16.row.col.f32.bf16.bf16.f32 "
                        "{%0,%1,%2,%3},{%4,%5,%6,%7},{%8,%9},{%0,%1,%2,%3};"
                        : "+f"(acc[mi][ni][0]), "+f"(acc[mi][ni][1]),
                          "+f"(acc[mi][ni][2]), "+f"(acc[mi][ni][3])
                        : "r"(afr[mi][0]), "r"(afr[mi][1]), "r"(afr[mi][2]), "r"(afr[mi][3]),
                          "r"(bfr[ni][0]), "r"(bfr[ni][1]));
                }
        }
    }

#pragma unroll
    for (int mi = 0; mi < 2; mi++) {
        int r0 = m0 + wm * 32 + mi * 16 + g;
#pragma unroll
        for (int ni = 0; ni < 8; ni++) {
            int col = n0 + wn * 64 + ni * 8 + 2 * c;
            float e2a = __ldg(&g_e2[col]);
            float e2b = __ldg(&g_e2[col + 1]);
            float2 v0 = make_float2(e2a - 2.f * acc[mi][ni][0], e2b - 2.f * acc[mi][ni][1]);
            float2 v1 = make_float2(e2a - 2.f * acc[mi][ni][2], e2b - 2.f * acc[mi][ni][3]);
            *(float2*)&S[(size_t)r0 * KCB + col] = v0;
            *(float2*)&S[(size_t)(r0 + 8) * KCB + col] = v1;
        }
    }
}

// ================= K3: approx argmin + exact fp64 refine =================
__global__ void k_argmin(const float* __restrict__ S, const float* __restrict__ emb) {
    __shared__ float xs[8][DDIM];
    __shared__ int candk[8][32];
    __shared__ int candn[8];
    __shared__ double bl;

    int tid = threadIdx.x;
    int w = tid >> 5, lane = tid & 31;
    int n = blockIdx.x * 8 + w;

    if (lane == 0) candn[w] = 0;
    if (tid == 0) bl = 0.0;
    __syncthreads();

    {
        const float4* xr = (const float4*)&g_flat[(size_t)n * DDIM];
        float4 a = xr[lane * 2], b2 = xr[lane * 2 + 1];
        *(float4*)&xs[w][lane * 8]     = a;
        *(float4*)&xs[w][lane * 8 + 4] = b2;
    }

    const float2* sr = (const float2*)&S[(size_t)n * KCB];
    float2 v[16];
    float mn = 3.4e38f;
#pragma unroll
    for (int i = 0; i < 16; i++) {
        v[i] = sr[i * 32 + lane];
        mn = fminf(mn, fminf(v[i].x, v[i].y));
    }
#pragma unroll
    for (int off = 16; off > 0; off >>= 1) mn = fminf(mn, __shfl_xor_sync(0xffffffffu, mn, off));

    float thr = mn + MARGIN;
#pragma unroll
    for (int i = 0; i < 16; i++) {
        if (v[i].x <= thr) {
            int p = atomicAdd(&candn[w], 1);
            if (p < 32) candk[w][p] = (i * 32 + lane) * 2;
        }
        if (v[i].y <= thr) {
            int p = atomicAdd(&candn[w], 1);
            if (p < 32) candk[w][p] = (i * 32 + lane) * 2 + 1;
        }
    }
    __syncwarp();
    int nc = candn[w]; if (nc > 32) nc = 32;

    double bestd = 1e300; int bestk = KCB;
    for (int ci = 0; ci < nc; ci++) {
        int kc = candk[w][ci];
        const float* er = &emb[(size_t)kc * DDIM];
        double part = 0.0;
#pragma unroll
        for (int d = lane; d < DDIM; d += 32) {
            double df = (double)xs[w][d] - (double)__ldg(&er[d]);
            part += df * df;
        }
#pragma unroll
        for (int off = 16; off > 0; off >>= 1)
            part += __shfl_xor_sync(0xffffffffu, part, off);
        if (part < bestd || (part == bestd && kc < bestk)) { bestd = part; bestk = kc; }
    }
    if (lane == 0) {
        g_idx[n] = bestk;
        atomicAdd(&g_counts[bestk], 1);
        atomicAdd(&bl, bestd);
    }
    __syncthreads();
    if (tid == 0) atomicAdd(&g_loss, bl);
}

// ================= K4: encodings zero-fill + ones =================
__global__ void k_zero_enc(float2* __restrict__ enc2) {
    size_t i = (size_t)blockIdx.x * blockDim.x + threadIdx.x;
    enc2[i] = make_float2(0.f, 0.f);
}
__global__ void k_ones(float* __restrict__ enc) {
    int n = blockIdx.x * 256 + threadIdx.x;
    enc[(size_t)n * KCB + g_idx[n]] = 1.0f;
}

// ================= K5: quantized output (NCHW), smem-tiled =================
__global__ void k_out(float* __restrict__ out, const float* __restrict__ emb) {
    __shared__ float tile[32][257];
    __shared__ int kk[32];
    int tid = threadIdx.x;
    int b = blockIdx.y;
    int hw0 = blockIdx.x * 32;

    if (tid < 32) kk[tid] = g_idx[b * 1024 + hw0 + tid];
    __syncthreads();
#pragma unroll 4
    for (int tl = 0; tl < 32; tl++) {
        tile[tl][tid] = __ldg(&emb[((size_t)kk[tl] << 8) + tid]);
    }
    __syncthreads();
    int hw = tid & 31;
    int cb = tid >> 5;          // 0..7
#pragma unroll 4
    for (int cc = 0; cc < 32; cc++) {
        int ch = cb * 32 + cc;
        out[((size_t)(b * 256 + ch) << 10) + hw0 + hw] = tile[hw][ch];
    }
}

// ================= K6: finalize cluster / entropy / loss + prefix =================
__global__ void k_finalize(const float* __restrict__ ema_cs,
                           float* __restrict__ cluster_o,
                           float* __restrict__ loss_o,
                           float* __restrict__ ent_o) {
    __shared__ float fs[1024];
    __shared__ int   is_[1024];
    int t = threadIdx.x;
    int cnt = g_counts[t];

    is_[t] = cnt; __syncthreads();
    for (int off = 1; off < 1024; off <<= 1) {
        int v2 = (t >= off) ? is_[t - off] : 0;
        __syncthreads();
        is_[t] += v2;
        __syncthreads();
    }
    g_start[t] = is_[t] - cnt;

    float cl = ema_cs[t] * DECAYF + ONE_M_DECAY * (float)cnt;
    fs[t] = cl; __syncthreads();
    for (int s = 512; s > 0; s >>= 1) { if (t < s) fs[t] += fs[t + s]; __syncthreads(); }
    float nsum = fs[0]; __syncthreads();

    float cln = ((cl + EPSF) / (nsum + 1024.0f * EPSF)) * nsum;
    g_cluster[t] = cln;
    cluster_o[t] = cln;

    float p = (float)cnt * (1.0f / 65536.0f);
    float e = -p * logf(p + 1e-10f);
    fs[t] = e; __syncthreads();
    for (int s = 512; s > 0; s >>= 1) { if (t < s) fs[t] += fs[t + s]; __syncthreads(); }
    if (t == 0) {
        ent_o[0] = fs[0];
        loss_o[0] = (float)(0.25 * g_loss / 16777216.0);
    }
}

// ================= K7: bucket fill =================
__global__ void k_bucket() {
    int n = blockIdx.x * 256 + threadIdx.x;
    int k = g_idx[n];
    int p = atomicAdd(&g_pos[k], 1);
    g_bucket[g_start[k] + p] = n;
}

// ================= K8: dw + new_ema_w + new_embedding =================
__global__ void k_emaw(const float* __restrict__ ema_w,
                       float* __restrict__ emaw_o,
                       float* __restrict__ emb_o) {
    int k = blockIdx.x, d = threadIdx.x;
    int cnt = g_counts[k], st = g_start[k];
    float acc = 0.f;
    for (int i = 0; i < cnt; i++) {
        int n = g_bucket[st + i];
        acc += g_flat[(size_t)n * DDIM + d];
    }
    float wv = ema_w[(size_t)k * DDIM + d] * DECAYF + ONE_M_DECAY * acc;
    emaw_o[(size_t)k * DDIM + d] = wv;
    emb_o[(size_t)k * DDIM + d] = wv / g_cluster[k];
}

// ================= launch =================
extern "C" void kernel_launch(void* const* d_in, const int* in_sizes, int n_in,
                              void* d_out, int out_size) {
    const float* inputs    = (const float*)d_in[0];
    const float* embedding = (const float*)d_in[1];
    const float* ema_cs    = (const float*)d_in[2];
    const float* ema_w     = (const float*)d_in[3];

    float* out     = (float*)d_out;
    float* loss_o  = out + OFF_LOSS;
    float* ent_o   = out + OFF_ENT;
    float* enc     = out + OFF_ENC;
    float* clus_o  = out + OFF_CLUSTER;
    float* emaw_o  = out + OFF_EMAW;
    float* emb_o   = out + OFF_EMB;

    k_init<<<1, 1024>>>();
    k_transpose<<<dim3(32, 8, 64), dim3(32, 8)>>>(inputs);
    k_embprep<<<KCB, 256>>>(embedding);
    k_gemm<<<dim3(NTOK / BM, KCB / BN), 256>>>(enc);
    k_argmin<<<NTOK / 8, 256>>>(enc, embedding);
    k_zero_enc<<<131072, 256>>>((float2*)enc);
    k_ones<<<NTOK / 256, 256>>>(enc);
    k_out<<<dim3(32, 64), 256>>>(out, embedding);
    k_finalize<<<1, 1024>>>(ema_cs, clus_o, loss_o, ent_o);
    k_bucket<<<NTOK / 256, 256>>>();
    k_emaw<<<KCB, 256>>>(ema_w, emaw_o, emb_o);
}